// round 9
// baseline (speedup 1.0000x reference)
#include <cuda_runtime.h>

#define BB 8
#define CC 256
#define HH 96
#define WW 96
#define HS 192
#define WS 192
#define OC 32
#define GG 4
#define CG 64   // CC/GG

typedef unsigned long long u64;

// transposed weights: g_wT[c*32 + o]
__device__ float g_wT[CC * OC];

#define FMA_F32X2(d, a, b) \
    asm("fma.rn.f32x2 %0, %1, %2, %0;" : "+l"(d) : "l"(a), "l"(b))
#define PACK_F32X2(out, lo, hi) \
    asm("mov.b64 %0, {%1, %2};" : "=l"(out) : "f"(lo), "f"(hi))
#define UNPACK_F32X2(lo, hi, in) \
    asm("mov.b64 {%0, %1}, %2;" : "=f"(lo), "=f"(hi) : "l"(in))

// ---------------------------------------------------------------------------
// Kernel 0: transpose w [32,256] -> g_wT [256,32]  (tiny, one-off)
// ---------------------------------------------------------------------------
__global__ void transpose_w_kernel(const float* __restrict__ w)
{
    int f = blockIdx.x * 256 + threadIdx.x;   // 0..8191
    int c = f >> 5, o = f & 31;
    g_wT[f] = w[o * CC + c];
}

// ---------------------------------------------------------------------------
// Fused kernel: block = (batch b, 4-row output band). 192 threads.
//  Phase 1 (conv): thread = one low-res pixel of the band's 2 source rows.
//    256-ch dot product, double-buffered x loads, FFMA2 accumulators,
//    weights via broadcast LDG.128 (L1-hot). tanh -> offsets into SMEM.
//  Phase 2 (gather): thread = 2 ws-pair slots x 4 groups x 64 channels.
//    Offsets straight from SMEM; streaming STG.64 pair stores.
// ---------------------------------------------------------------------------
__global__ __launch_bounds__(192) void fused_kernel(
    const float* __restrict__ x, const float* __restrict__ bias,
    float* __restrict__ out)
{
    // soff[(g*4 + hs_sub)*WS + ws] = (offx, offy)   : 3072 float2 = 24 KB
    __shared__ __align__(16) float2 soff[GG * 4 * WS];

    int tid = threadIdx.x;
    int b   = blockIdx.x / (HS / 4);     // 0..7
    int r   = blockIdx.x - b * (HS / 4); // 0..47
    int hs0 = r * 4;                     // output rows hs0..hs0+3
    int h0  = r * 2;                     // source rows h0, h0+1

    // ===================== Phase 1: conv + tanh -> SMEM =====================
    {
        int hr = tid / WW;               // 0..1
        int wp = tid - hr * WW;          // 0..95
        int h  = h0 + hr;

        u64 acc[OC / 2];
        #pragma unroll
        for (int q = 0; q < OC / 2; ++q) acc[q] = 0ull;

        const float* xp = x + (b * CC) * (HH * WW) + h * WW + wp;
        float xa[8], xb[8];
        #pragma unroll
        for (int u = 0; u < 8; ++u) xa[u] = __ldg(xp + u * (HH * WW));

        #pragma unroll 1
        for (int c0 = 0; c0 < CC; c0 += 8) {
            if (c0 + 8 < CC) {
                #pragma unroll
                for (int u = 0; u < 8; ++u)          // prefetch next batch
                    xb[u] = __ldg(xp + (c0 + 8 + u) * (HH * WW));
            }
            #pragma unroll
            for (int u = 0; u < 8; ++u) {
                u64 xx;
                PACK_F32X2(xx, xa[u], xa[u]);
                const ulonglong2* wr =
                    (const ulonglong2*)(g_wT + (c0 + u) * OC);
                #pragma unroll
                for (int q = 0; q < OC / 4; ++q) {   // 8 x LDG.128 broadcast
                    ulonglong2 wv = __ldg(wr + q);
                    FMA_F32X2(acc[2 * q + 0], xx, wv.x);
                    FMA_F32X2(acc[2 * q + 1], xx, wv.y);
                }
            }
            #pragma unroll
            for (int u = 0; u < 8; ++u) xa[u] = xb[u];
        }

        float offv[OC];
        #pragma unroll
        for (int q = 0; q < OC / 2; ++q) {
            float a0, a1;
            UNPACK_F32X2(a0, a1, acc[q]);
            offv[2 * q + 0] = tanhf(a0 + __ldg(bias + 2 * q));
            offv[2 * q + 1] = tanhf(a1 + __ldg(bias + 2 * q + 1));
        }
        // o = co*4 + i*2 + j ; co = g*2 + k (k: 0=x-comp, 1=y-comp)
        #pragma unroll
        for (int g = 0; g < GG; ++g)
            #pragma unroll
            for (int i = 0; i < 2; ++i)
                #pragma unroll
                for (int j = 0; j < 2; ++j) {
                    float2 v;
                    v.x = offv[(g * 2 + 0) * 4 + i * 2 + j];
                    v.y = offv[(g * 2 + 1) * 4 + i * 2 + j];
                    soff[(g * 4 + (2 * hr + i)) * WS + (2 * wp + j)] = v;
                }
    }
    __syncthreads();

    // ===================== Phase 2: gather ==================================
    // pair slots pp = tid, tid+192 ; pp -> (hs_sub = pp/96, ws0 = 2*(pp%96))
    int hsub[2], wcol[2];
    #pragma unroll
    for (int k = 0; k < 2; ++k) {
        int pp  = tid + k * 192;
        hsub[k] = pp / (WS / 2);
        wcol[k] = 2 * (pp - hsub[k] * (WS / 2));
    }

    #pragma unroll 1
    for (int g = 0; g < GG; ++g) {
        int   i00[4], dxo[4], dyo[4];
        float w00[4], w01[4], w10[4], w11[4];
        #pragma unroll
        for (int k = 0; k < 2; ++k) {
            // both pixels' offsets: one LDS.128
            float4 oo = *(const float4*)&soff[(g * 4 + hsub[k]) * WS + wcol[k]];
            float ox[2] = {oo.x, oo.z};
            float oy[2] = {oo.y, oo.w};
            #pragma unroll
            for (int j = 0; j < 2; ++j) {
                int e = k * 2 + j;
                float gx = (float)(wcol[k] + j)      * 0.5f - 0.25f + 6.0f * ox[j];
                float gy = (float)(hs0 + hsub[k])    * 0.5f - 0.25f + 6.0f * oy[j];
                gx = fminf(fmaxf(gx, 0.0f), (float)(WW - 1));
                gy = fminf(fmaxf(gy, 0.0f), (float)(HH - 1));
                int x0 = (int)gx;
                int y0 = (int)gy;
                float wx = gx - (float)x0;
                float wy = gy - (float)y0;
                dxo[e] = (x0 < WW - 1) ? 1  : 0;
                dyo[e] = (y0 < HH - 1) ? WW : 0;
                i00[e] = y0 * WW + x0;
                w00[e] = (1.0f - wx) * (1.0f - wy);
                w01[e] = wx * (1.0f - wy);
                w10[e] = (1.0f - wx) * wy;
                w11[e] = wx * wy;
            }
        }

        const float* xp = x + (b * CC + g * CG) * (HH * WW);
        float* op0 = out + ((b * CC + g * CG) * HS + hs0 + hsub[0]) * WS + wcol[0];
        float* op1 = out + ((b * CC + g * CG) * HS + hs0 + hsub[1]) * WS + wcol[1];

        #pragma unroll 2
        for (int c = 0; c < CG; ++c) {
            float v[16];
            #pragma unroll
            for (int e = 0; e < 4; ++e) {            // 16 independent LDGs
                v[4 * e + 0] = __ldg(xp + i00[e]);
                v[4 * e + 1] = __ldg(xp + i00[e] + dxo[e]);
                v[4 * e + 2] = __ldg(xp + i00[e] + dyo[e]);
                v[4 * e + 3] = __ldg(xp + i00[e] + dyo[e] + dxo[e]);
            }
            float2 r0, r1;
            r0.x = v[0]  * w00[0] + v[1]  * w01[0] + v[2]  * w10[0] + v[3]  * w11[0];
            r0.y = v[4]  * w00[1] + v[5]  * w01[1] + v[6]  * w10[1] + v[7]  * w11[1];
            r1.x = v[8]  * w00[2] + v[9]  * w01[2] + v[10] * w10[2] + v[11] * w11[2];
            r1.y = v[12] * w00[3] + v[13] * w01[3] + v[14] * w10[3] + v[15] * w11[3];
            __stcs((float2*)op0, r0);
            __stcs((float2*)op1, r1);
            xp  += HH * WW;
            op0 += HS * WS;
            op1 += HS * WS;
        }
    }
}

extern "C" void kernel_launch(void* const* d_in, const int* in_sizes, int n_in,
                              void* d_out, int out_size) {
    const float* x    = (const float*)d_in[0];
    const float* w    = (const float*)d_in[1];
    const float* bias = (const float*)d_in[2];
    float* out        = (float*)d_out;

    transpose_w_kernel<<<(CC * OC) / 256, 256>>>(w);
    fused_kernel<<<BB * (HS / 4), 192>>>(x, bias, out);
}

// round 13
// speedup vs baseline: 1.5684x; 1.5684x over previous
#include <cuda_runtime.h>

#define BB 8
#define CC 256
#define HH 96
#define WW 96
#define HS 192
#define WS 192
#define OC 32
#define GG 4
#define CG 64   // CC/GG

typedef unsigned long long u64;

// Offset field scratch: [B][G][HS][WS] x float2 (x-offset, y-offset) interleaved
__device__ float g_off[BB * GG * HS * WS * 2];

#define FMA_F32X2(d, a, b) \
    asm("fma.rn.f32x2 %0, %1, %2, %0;" : "+l"(d) : "l"(a), "l"(b))
#define PACK_F32X2(out, lo, hi) \
    asm("mov.b64 %0, {%1, %2};" : "=l"(out) : "f"(lo), "f"(hi))
#define UNPACK_F32X2(lo, hi, in) \
    asm("mov.b64 {%0, %1}, %2;" : "=f"(lo), "=f"(hi) : "l"(in))

// ---------------------------------------------------------------------------
// Kernel 1: 1x1 conv (32 outputs over 256 channels) + tanh + pixel_shuffle(2)
// One thread = one low-res pixel. DOUBLE-BUFFERED 8-deep LDG prefetch so
// batch N+1 loads issue before batch N is consumed. fma.rn.f32x2 accums,
// weights broadcast from smem as f32x2 pairs.
// ---------------------------------------------------------------------------
__global__ __launch_bounds__(256) void conv_offset_kernel(
    const float* __restrict__ x, const float* __restrict__ w,
    const float* __restrict__ bias)
{
    __shared__ __align__(16) float wT[CC * OC];  // wT[c*32 + o]
    int tid = threadIdx.x;
    #pragma unroll
    for (int k = 0; k < (CC * OC) / 256; ++k) {
        int flat = tid + k * 256;
        int c = flat >> 5, o = flat & 31;
        wT[flat] = w[o * CC + c];
    }
    __syncthreads();

    int p   = blockIdx.x * 256 + tid;       // 0 .. B*H*W-1 (73728)
    int b   = p / (HH * WW);
    int rem = p - b * (HH * WW);
    int h   = rem / WW;
    int wp  = rem - h * WW;

    u64 acc[OC / 2];
    #pragma unroll
    for (int q = 0; q < OC / 2; ++q)
        PACK_F32X2(acc[q], bias[2 * q], bias[2 * q + 1]);

    const float* xp = x + (b * CC) * (HH * WW) + h * WW + wp;

    float xa[8], xb[8];
    #pragma unroll
    for (int u = 0; u < 8; ++u)
        xa[u] = __ldg(xp + u * (HH * WW));

    #pragma unroll 1
    for (int c0 = 0; c0 < CC; c0 += 8) {
        if (c0 + 8 < CC) {
            #pragma unroll
            for (int u = 0; u < 8; ++u)             // prefetch next batch early
                xb[u] = __ldg(xp + (c0 + 8 + u) * (HH * WW));
        }
        #pragma unroll
        for (int u = 0; u < 8; ++u) {
            u64 xx;
            PACK_F32X2(xx, xa[u], xa[u]);
            const ulonglong2* wrow = (const ulonglong2*)(wT + (c0 + u) * OC);
            #pragma unroll
            for (int q = 0; q < OC / 4; ++q) {
                ulonglong2 wv = wrow[q];            // broadcast LDS.128
                FMA_F32X2(acc[2 * q + 0], xx, wv.x);
                FMA_F32X2(acc[2 * q + 1], xx, wv.y);
            }
        }
        #pragma unroll
        for (int u = 0; u < 8; ++u) xa[u] = xb[u];
    }

    // pixel_shuffle(2) + tanh + scatter into interleaved (x,y) offset field
    #pragma unroll
    for (int q = 0; q < OC / 2; ++q) {
        float a0, a1;
        UNPACK_F32X2(a0, a1, acc[q]);
        #pragma unroll
        for (int s = 0; s < 2; ++s) {
            int o    = 2 * q + s;
            float v  = tanhf(s ? a1 : a0);
            int co   = o >> 2;          // 0..7  channel after shuffle
            int i    = (o >> 1) & 1;    // row sub-position
            int j    = o & 1;           // col sub-position
            int gidx = co >> 1;         // group 0..3
            int k    = co & 1;          // 0 = x-offset, 1 = y-offset
            int hs = 2 * h + i, ws = 2 * wp + j;
            g_off[((((b * GG + gidx) * HS + hs) * WS + ws) << 1) + k] = v;
        }
    }
}

// ---------------------------------------------------------------------------
// Kernel 2: bilinear border grid_sample. One thread = 2 horizontally adjacent
// output pixels -> STG.64 streaming stores, one LDG.128 for both offset
// pairs, 8 independent gather LDGs per channel iteration, unroll 4.
// ---------------------------------------------------------------------------
__global__ __launch_bounds__(256) void gather_kernel(
    const float* __restrict__ x, float* __restrict__ out)
{
    const int tiles = (HS * WS / 2) / 256;  // 72 pair-tiles per (b,g)
    int bg   = blockIdx.x / tiles;          // 0..31 = b*4 + gidx
    int t    = (blockIdx.x - bg * tiles) * 256 + threadIdx.x;
    int hs   = t / (WS / 2);
    int ws0  = (t - hs * (WS / 2)) * 2;     // even column of the pair
    int b    = bg >> 2;
    int gidx = bg & 3;

    // both offset pairs in one LDG.128: (x0,y0,x1,y1)
    float4 oo = __ldg((const float4*)g_off + (((bg * HS + hs) * WS + ws0) >> 1));
    float offx[2] = {oo.x, oo.z};
    float offy[2] = {oo.y, oo.w};

    int   i00[2], dx[2], dy[2];
    float w00[2], w01[2], w10[2], w11[2];
    #pragma unroll
    for (int j = 0; j < 2; ++j) {
        // grid math collapsed: gx = (base_x + 0.125*off + 1)*48 - 0.5
        float gx = (float)(ws0 + j) * 0.5f - 0.25f + 6.0f * offx[j];
        float gy = (float)hs        * 0.5f - 0.25f + 6.0f * offy[j];
        gx = fminf(fmaxf(gx, 0.0f), (float)(WW - 1));
        gy = fminf(fmaxf(gy, 0.0f), (float)(HH - 1));
        int x0 = (int)gx;   // floor (gx >= 0)
        int y0 = (int)gy;
        float wx = gx - (float)x0;
        float wy = gy - (float)y0;
        dx[j]  = (x0 < WW - 1) ? 1  : 0;
        dy[j]  = (y0 < HH - 1) ? WW : 0;
        i00[j] = y0 * WW + x0;
        w00[j] = (1.0f - wx) * (1.0f - wy);
        w01[j] = wx * (1.0f - wy);
        w10[j] = (1.0f - wx) * wy;
        w11[j] = wx * wy;
    }

    const float* xp = x + (b * CC + gidx * CG) * (HH * WW);
    float*       op = out + ((b * CC + gidx * CG) * HS + hs) * WS + ws0;

    #pragma unroll 4
    for (int c = 0; c < CG; ++c) {
        float v[8];
        #pragma unroll
        for (int j = 0; j < 2; ++j) {               // 8 independent LDGs
            v[4 * j + 0] = __ldg(xp + i00[j]);
            v[4 * j + 1] = __ldg(xp + i00[j] + dx[j]);
            v[4 * j + 2] = __ldg(xp + i00[j] + dy[j]);
            v[4 * j + 3] = __ldg(xp + i00[j] + dy[j] + dx[j]);
        }
        float2 r;
        r.x = v[0] * w00[0] + v[1] * w01[0] + v[2] * w10[0] + v[3] * w11[0];
        r.y = v[4] * w00[1] + v[5] * w01[1] + v[6] * w10[1] + v[7] * w11[1];
        __stcs((float2*)op, r);                     // streaming store
        xp += HH * WW;
        op += HS * WS;
    }
}

extern "C" void kernel_launch(void* const* d_in, const int* in_sizes, int n_in,
                              void* d_out, int out_size) {
    const float* x    = (const float*)d_in[0];
    const float* w    = (const float*)d_in[1];
    const float* bias = (const float*)d_in[2];
    float* out        = (float*)d_out;

    conv_offset_kernel<<<(BB * HH * WW) / 256, 256>>>(x, w, bias);
    gather_kernel<<<BB * GG * ((HS * WS / 2) / 256), 256>>>(x, out);
}